// round 8
// baseline (speedup 1.0000x reference)
#include <cuda_runtime.h>
#include <math.h>

constexpr int C   = 32;
constexpr int N_H = 40000, D_H = 16;
constexpr int N_O = 20000, D_O = 48;

constexpr int WPB   = 8;
constexpr int BLOCK = WPB * 32;          // 256 threads, warp = 1 atom
constexpr int NB_O  = N_O / WPB;         // 2500
constexpr int NB_H  = N_H / WPB;         // 5000
constexpr int NB    = NB_O + NB_H;       // 7500; bid%3==0 -> O else H

typedef unsigned long long u64;

// ---- packed f32x2 helpers (Blackwell FFMA2 path, PTX-only) ----
__device__ __forceinline__ u64 fma2(u64 a, u64 b, u64 c) {
    u64 d;
    asm("fma.rn.f32x2 %0, %1, %2, %3;" : "=l"(d) : "l"(a), "l"(b), "l"(c));
    return d;
}
__device__ __forceinline__ u64 add2(u64 a, u64 b) {
    u64 d;
    asm("add.rn.f32x2 %0, %1, %2;" : "=l"(d) : "l"(a), "l"(b));
    return d;
}
__device__ __forceinline__ u64 mul2(u64 a, u64 b) {
    u64 d;
    asm("mul.rn.f32x2 %0, %1, %2;" : "=l"(d) : "l"(a), "l"(b));
    return d;
}
__device__ __forceinline__ u64 pack2(float lo, float hi) {
    u64 d;
    asm("mov.b64 %0, {%1, %2};" : "=l"(d) : "r"(__float_as_uint(lo)), "r"(__float_as_uint(hi)));
    return d;
}
__device__ __forceinline__ void unpack2(u64 v, float& lo, float& hi) {
    unsigned int a, b;
    asm("mov.b64 {%0, %1}, %2;" : "=r"(a), "=r"(b) : "l"(v));
    lo = __uint_as_float(a);
    hi = __uint_as_float(b);
}

// Folded lower-triangular S, row i padded to a multiple of 4 floats (zeros).
__host__ __device__ constexpr int rowLen(int i) { return (i + 4) & ~3; }
__host__ __device__ constexpr int rowOff(int i) {
    int s = 0;
    for (int t = 0; t < i; t++) s += rowLen(t);
    return s;
}
template <int D>
__host__ __device__ constexpr int triTot() { return rowOff(D); }

template <int D>
__device__ void fillS(const float* __restrict__ S, float* Sp) {
    constexpr int TOT = triTot<D>();
    for (int k = threadIdx.x; k < TOT; k += BLOCK) Sp[k] = 0.0f;
    __syncthreads();
    for (int k = threadIdx.x; k < D * D; k += BLOCK) {
        int i = k / D;
        int j = k - i * D;
        if (j <= i) {
            int off = 0;
            for (int t = 0; t < i; t++) off += ((t + 4) & ~3);
            Sp[off + j] = S[k] * (j == i ? 1.0f : 2.0f);
        }
    }
    __syncthreads();
}

// Warp = 1 atom, lane = channel; rows packed in pairs into u64.
template <int D>
__device__ __forceinline__ void processAtom(const float* __restrict__ x,
                                            float* __restrict__ out,
                                            const float* __restrict__ Sp,
                                            int baseRow, int lane) {
    constexpr int KP = D / 2;
    const float* xp = x + (size_t)baseRow * C + lane;

    u64 y2[KP];
#pragma unroll
    for (int k = 0; k < KP; k++) {
        float a = __ldg(xp + (2 * k + 0) * C);
        float b = __ldg(xp + (2 * k + 1) * C);
        y2[k] = pack2(a, b);
    }

    u64 acc2 = 0ull;
#pragma unroll
    for (int k = 0; k < KP; k++) {
        const int i0 = 2 * k;
        const int nc = k / 2 + 1;  // float4 chunks for both rows of the pair
        const ulonglong2* r0 = reinterpret_cast<const ulonglong2*>(Sp + rowOff(i0));
        const ulonglong2* r1 = reinterpret_cast<const ulonglong2*>(Sp + rowOff(i0 + 1));
        u64 ue0 = 0ull, ue1 = 0ull, uo0 = 0ull, uo1 = 0ull;
#pragma unroll
        for (int jc = 0; jc < nc; jc++) {
            ulonglong2 a = r0[jc];  // floats (4jc..4jc+3) of row 2k (broadcast)
            ulonglong2 b = r1[jc];  // same columns of row 2k+1
            ue0 = fma2(a.x, y2[2 * jc + 0], ue0);
            ue1 = fma2(a.y, y2[2 * jc + 1], ue1);
            uo0 = fma2(b.x, y2[2 * jc + 0], uo0);
            uo1 = fma2(b.y, y2[2 * jc + 1], uo1);
        }
        u64 ue = add2(ue0, ue1);
        u64 uo = add2(uo0, uo1);
        float el, eh, ol, oh;
        unpack2(ue, el, eh);
        unpack2(uo, ol, oh);
        acc2 = fma2(y2[k], pack2(el + eh, ol + oh), acc2);
    }

    float alo, ahi;
    unpack2(acc2, alo, ahi);
    const float inv  = 1.0f / (sqrtf(alo + ahi) + 1e-6f);
    const u64   inv2 = pack2(inv, inv);

    float* op = out + (size_t)baseRow * C + lane;
#pragma unroll
    for (int k = 0; k < KP; k++) {
        u64 m = mul2(y2[k], inv2);
        float s0, s1;
        unpack2(m, s0, s1);
        op[(2 * k + 0) * C] = s0;
        op[(2 * k + 1) * C] = s1;
    }
}

// Fused kernel: every 3rd block is an O block, the other two are H blocks.
// This pins a ~1:2 O:H mix on every SM for the whole run so the L1-bound O
// work and the DRAM-bound H work overlap structurally.
__global__ __launch_bounds__(BLOCK, 3) void l2norm_fused(
    const float* __restrict__ x,
    const float* __restrict__ S_H, const float* __restrict__ S_O,
    const int* __restrict__ idx_H, const int* __restrict__ idx_O,
    float* __restrict__ out) {
    __shared__ __align__(16) float Sp[triTot<D_O>()];

    const int warp = threadIdx.x >> 5;
    const int lane = threadIdx.x & 31;
    const int bid  = blockIdx.x;
    const int typeO = (bid % 3 == 0);

    if (typeO) {
        fillS<D_O>(S_O, Sp);
        const int atom = (bid / 3) * WPB + warp;
        const int baseRow = __ldg(idx_O + atom * D_O);
        processAtom<D_O>(x, out, Sp, baseRow, lane);
    } else {
        fillS<D_H>(S_H, Sp);
        const int atom = (bid - bid / 3 - 1) * WPB + warp;  // 0..NB_H-1
        const int baseRow = __ldg(idx_H + atom * D_H);
        processAtom<D_H>(x, out, Sp, baseRow, lane);
    }
}

extern "C" void kernel_launch(void* const* d_in, const int* in_sizes, int n_in,
                              void* d_out, int out_size) {
    const float* x     = (const float*)d_in[0];
    const float* S_H   = (const float*)d_in[1];
    const float* S_O   = (const float*)d_in[2];
    const int*   idx_H = (const int*)d_in[3];
    const int*   idx_O = (const int*)d_in[4];
    float* out = (float*)d_out;

    l2norm_fused<<<NB, BLOCK>>>(x, S_H, S_O, idx_H, idx_O, out);
}

// round 9
// speedup vs baseline: 1.0747x; 1.0747x over previous
#include <cuda_runtime.h>
#include <math.h>

constexpr int C   = 32;
constexpr int N_H = 40000, D_H = 16;
constexpr int N_O = 20000, D_O = 48;

constexpr int WPB   = 8;
constexpr int BLOCK = WPB * 32;          // 256 threads, warp = 1 atom
constexpr int NB_O  = N_O / WPB;         // 2500
constexpr int NB_H  = N_H / WPB;         // 5000
constexpr int NB    = NB_O + NB_H;       // 7500; bid%3==0 -> O else H

typedef unsigned long long u64;

// ---- packed f32x2 helpers (Blackwell FFMA2 path, PTX-only) ----
__device__ __forceinline__ u64 fma2(u64 a, u64 b, u64 c) {
    u64 d;
    asm("fma.rn.f32x2 %0, %1, %2, %3;" : "=l"(d) : "l"(a), "l"(b), "l"(c));
    return d;
}
__device__ __forceinline__ u64 add2(u64 a, u64 b) {
    u64 d;
    asm("add.rn.f32x2 %0, %1, %2;" : "=l"(d) : "l"(a), "l"(b));
    return d;
}
__device__ __forceinline__ u64 mul2(u64 a, u64 b) {
    u64 d;
    asm("mul.rn.f32x2 %0, %1, %2;" : "=l"(d) : "l"(a), "l"(b));
    return d;
}
__device__ __forceinline__ u64 pack2(float lo, float hi) {
    u64 d;
    asm("mov.b64 %0, {%1, %2};" : "=l"(d) : "r"(__float_as_uint(lo)), "r"(__float_as_uint(hi)));
    return d;
}
__device__ __forceinline__ void unpack2(u64 v, float& lo, float& hi) {
    unsigned int a, b;
    asm("mov.b64 {%0, %1}, %2;" : "=r"(a), "=r"(b) : "l"(v));
    lo = __uint_as_float(a);
    hi = __uint_as_float(b);
}

// Folded lower-triangular S, row i padded to a multiple of 4 floats (zeros).
__host__ __device__ constexpr int rowLen(int i) { return (i + 4) & ~3; }
__host__ __device__ constexpr int rowOff(int i) {
    int s = 0;
    for (int t = 0; t < i; t++) s += rowLen(t);
    return s;
}
template <int D>
__host__ __device__ constexpr int triTot() { return rowOff(D); }

template <int D>
__device__ void fillS(const float* __restrict__ S, float* Sp) {
    constexpr int TOT = triTot<D>();
    for (int k = threadIdx.x; k < TOT; k += BLOCK) Sp[k] = 0.0f;
    __syncthreads();
    for (int k = threadIdx.x; k < D * D; k += BLOCK) {
        int i = k / D;
        int j = k - i * D;
        if (j <= i) {
            int off = 0;
            for (int t = 0; t < i; t++) off += ((t + 4) & ~3);
            Sp[off + j] = S[k] * (j == i ? 1.0f : 2.0f);
        }
    }
    __syncthreads();
}

// Warp = 1 atom, lane = channel; rows packed in pairs into u64.
// Register-lean variant: per row-pair, process the even row's chunks then the
// odd row's chunks sequentially so only one 16B S chunk + 2 accumulators are
// live at any point (targets a 64-register kernel for 4 blocks/SM).
template <int D>
__device__ __forceinline__ void processAtom(const float* __restrict__ x,
                                            float* __restrict__ out,
                                            const float* __restrict__ Sp,
                                            int baseRow, int lane) {
    constexpr int KP = D / 2;
    const float* xp = x + (size_t)baseRow * C + lane;

    u64 y2[KP];
#pragma unroll
    for (int k = 0; k < KP; k++) {
        float a = __ldg(xp + (2 * k + 0) * C);
        float b = __ldg(xp + (2 * k + 1) * C);
        y2[k] = pack2(a, b);
    }

    u64 acc2 = 0ull;
#pragma unroll
    for (int k = 0; k < KP; k++) {
        const int i0 = 2 * k;
        const int nc = k / 2 + 1;  // float4 chunks per row of the pair
        const ulonglong2* r0 = reinterpret_cast<const ulonglong2*>(Sp + rowOff(i0));
        const ulonglong2* r1 = reinterpret_cast<const ulonglong2*>(Sp + rowOff(i0 + 1));

        // even row 2k
        u64 e0 = 0ull, e1 = 0ull;
#pragma unroll
        for (int jc = 0; jc < nc; jc++) {
            ulonglong2 a = r0[jc];  // LDS.128 broadcast
            e0 = fma2(a.x, y2[2 * jc + 0], e0);
            e1 = fma2(a.y, y2[2 * jc + 1], e1);
        }
        float el, eh;
        unpack2(add2(e0, e1), el, eh);

        // odd row 2k+1
        u64 o0 = 0ull, o1 = 0ull;
#pragma unroll
        for (int jc = 0; jc < nc; jc++) {
            ulonglong2 b = r1[jc];
            o0 = fma2(b.x, y2[2 * jc + 0], o0);
            o1 = fma2(b.y, y2[2 * jc + 1], o1);
        }
        float ol, oh;
        unpack2(add2(o0, o1), ol, oh);

        acc2 = fma2(y2[k], pack2(el + eh, ol + oh), acc2);
    }

    float alo, ahi;
    unpack2(acc2, alo, ahi);
    const float inv  = 1.0f / (sqrtf(alo + ahi) + 1e-6f);
    const u64   inv2 = pack2(inv, inv);

    float* op = out + (size_t)baseRow * C + lane;
#pragma unroll
    for (int k = 0; k < KP; k++) {
        u64 m = mul2(y2[k], inv2);
        float s0, s1;
        unpack2(m, s0, s1);
        op[(2 * k + 0) * C] = s0;
        op[(2 * k + 1) * C] = s1;
    }
}

// Fused kernel: every 3rd block is an O block, the other two are H blocks,
// so each SM holds a ~1:2 O:H mix. Forced to <=64 regs -> 4 blocks/SM
// (32 warps) to break the 80-reg/24-warp latency wall seen in R8.
__global__ __launch_bounds__(BLOCK, 4) void l2norm_fused(
    const float* __restrict__ x,
    const float* __restrict__ S_H, const float* __restrict__ S_O,
    const int* __restrict__ idx_H, const int* __restrict__ idx_O,
    float* __restrict__ out) {
    __shared__ __align__(16) float Sp[triTot<D_O>()];

    const int warp = threadIdx.x >> 5;
    const int lane = threadIdx.x & 31;
    const int bid  = blockIdx.x;

    if (bid % 3 == 0) {
        fillS<D_O>(S_O, Sp);
        const int atom = (bid / 3) * WPB + warp;
        const int baseRow = __ldg(idx_O + atom * D_O);
        processAtom<D_O>(x, out, Sp, baseRow, lane);
    } else {
        fillS<D_H>(S_H, Sp);
        const int atom = (bid - bid / 3 - 1) * WPB + warp;  // 0..NB_H-1
        const int baseRow = __ldg(idx_H + atom * D_H);
        processAtom<D_H>(x, out, Sp, baseRow, lane);
    }
}

extern "C" void kernel_launch(void* const* d_in, const int* in_sizes, int n_in,
                              void* d_out, int out_size) {
    const float* x     = (const float*)d_in[0];
    const float* S_H   = (const float*)d_in[1];
    const float* S_O   = (const float*)d_in[2];
    const int*   idx_H = (const int*)d_in[3];
    const int*   idx_O = (const int*)d_in[4];
    float* out = (float*)d_out;

    l2norm_fused<<<NB, BLOCK>>>(x, S_H, S_O, idx_H, idx_O, out);
}

// round 10
// speedup vs baseline: 1.0959x; 1.0198x over previous
#include <cuda_runtime.h>
#include <math.h>

constexpr int C   = 32;
constexpr int N_H = 40000, D_H = 16;
constexpr int N_O = 20000, D_O = 48;

constexpr int WPB   = 8;
constexpr int BLOCK = WPB * 32;
// warp = 2 atoms: lanes 0-15 atom A, lanes 16-31 atom B; lane owns channel pair.
constexpr int NB_O = N_O / (2 * WPB);  // 1250
constexpr int NB_H = N_H / (2 * WPB);  // 2500

typedef unsigned long long u64;

// ---- packed f32x2 helpers (Blackwell FFMA2 path, PTX-only) ----
__device__ __forceinline__ u64 fma2(u64 a, u64 b, u64 c) {
    u64 d;
    asm("fma.rn.f32x2 %0, %1, %2, %3;" : "=l"(d) : "l"(a), "l"(b), "l"(c));
    return d;
}
__device__ __forceinline__ u64 add2(u64 a, u64 b) {
    u64 d;
    asm("add.rn.f32x2 %0, %1, %2;" : "=l"(d) : "l"(a), "l"(b));
    return d;
}
__device__ __forceinline__ u64 mul2(u64 a, u64 b) {
    u64 d;
    asm("mul.rn.f32x2 %0, %1, %2;" : "=l"(d) : "l"(a), "l"(b));
    return d;
}
__device__ __forceinline__ u64 pack2(float lo, float hi) {
    u64 d;
    asm("mov.b64 %0, {%1, %2};" : "=l"(d) : "r"(__float_as_uint(lo)), "r"(__float_as_uint(hi)));
    return d;
}
__device__ __forceinline__ void unpack2(u64 v, float& lo, float& hi) {
    unsigned int a, b;
    asm("mov.b64 {%0, %1}, %2;" : "=r"(a), "=r"(b) : "l"(v));
    lo = __uint_as_float(a);
    hi = __uint_as_float(b);
}
// Duplicate one scalar into both halves of a u64 (single wide MOV).
__device__ __forceinline__ u64 dup2(float f) {
    u64 d;
    unsigned int r = __float_as_uint(f);
    asm("mov.b64 %0, {%1, %1};" : "=l"(d) : "r"(r));
    return d;
}

// Folded lower-triangular S (NON-duplicated), row i padded to mult of 4 floats.
__host__ __device__ constexpr int rowLen(int i) { return (i + 4) & ~3; }
__host__ __device__ constexpr int rowOff(int i) {
    int s = 0;
    for (int t = 0; t < i; t++) s += rowLen(t);
    return s;
}
template <int D>
__host__ __device__ constexpr int triTot() { return rowOff(D); }

template <int D>
__device__ void fillS(const float* __restrict__ S, float* Sp) {
    constexpr int TOT = triTot<D>();
    for (int k = threadIdx.x; k < TOT; k += BLOCK) Sp[k] = 0.0f;
    __syncthreads();
    for (int k = threadIdx.x; k < D * D; k += BLOCK) {
        int i = k / D;
        int j = k - i * D;
        if (j <= i) {
            int off = 0;
            for (int t = 0; t < i; t++) off += ((t + 4) & ~3);
            Sp[off + j] = S[k] * (j == i ? 1.0f : 2.0f);
        }
    }
    __syncthreads();
}

// Warp = 2 atoms (half-warp each), lane = channel pair (2cp, 2cp+1).
// Each LDS.128 brings 4 distinct S values serving BOTH atoms (half the
// per-atom shared traffic of the row-pair layout); scalars are duplicated
// register-side with 1-op wide MOVs. z_i stays packed per lane (2 channels),
// so there are no horizontal adds in the row loop.
template <int D>
__device__ __forceinline__ void processPair(const float* __restrict__ x,
                                            float* __restrict__ out,
                                            const float* __restrict__ Sp,
                                            int rowA, int rowB, int lane) {
    const int half = lane >> 4;
    const int cp   = lane & 15;
    const int baseRow = half ? rowB : rowA;

    const u64* xp = reinterpret_cast<const u64*>(x) + (size_t)baseRow * 16 + cp;

    u64 y2[D];
#pragma unroll
    for (int j = 0; j < D; j++) y2[j] = __ldg(xp + j * 16);

    u64 acc2 = 0ull;
#pragma unroll
    for (int i = 0; i < D; i++) {
        const int nc = i / 4 + 1;  // float4 chunks in padded row i
        const float4* rp = reinterpret_cast<const float4*>(Sp + rowOff(i));
        u64 u0 = 0ull, u1 = 0ull;
#pragma unroll
        for (int jc = 0; jc < nc; jc++) {
            float4 s = rp[jc];  // 4 distinct folded-S values (broadcast LDS.128)
            u0 = fma2(dup2(s.x), y2[4 * jc + 0], u0);
            u1 = fma2(dup2(s.y), y2[4 * jc + 1], u1);
            u0 = fma2(dup2(s.z), y2[4 * jc + 2], u0);
            u1 = fma2(dup2(s.w), y2[4 * jc + 3], u1);
        }
        acc2 = fma2(y2[i], add2(u0, u1), acc2);
    }

    float a0, a1;
    unpack2(acc2, a0, a1);
    const u64 inv2 = pack2(1.0f / (sqrtf(a0) + 1e-6f),
                           1.0f / (sqrtf(a1) + 1e-6f));

    u64* op = reinterpret_cast<u64*>(out) + (size_t)baseRow * 16 + cp;
#pragma unroll
    for (int j = 0; j < D; j++) op[j * 16] = mul2(y2[j], inv2);
}

__global__ __launch_bounds__(BLOCK, 2) void l2norm_O(
    const float* __restrict__ x, const float* __restrict__ S,
    const int* __restrict__ idx, float* __restrict__ out) {
    __shared__ __align__(16) float Sp[triTot<D_O>()];
    fillS<D_O>(S, Sp);
    const int warp = threadIdx.x >> 5;
    const int lane = threadIdx.x & 31;
    const int p = blockIdx.x * WPB + warp;
    const int rowA = __ldg(idx + (2 * p + 0) * D_O);
    const int rowB = __ldg(idx + (2 * p + 1) * D_O);
    processPair<D_O>(x, out, Sp, rowA, rowB, lane);
}

__global__ __launch_bounds__(BLOCK, 6) void l2norm_H(
    const float* __restrict__ x, const float* __restrict__ S,
    const int* __restrict__ idx, float* __restrict__ out) {
    __shared__ __align__(16) float Sp[triTot<D_H>()];
    fillS<D_H>(S, Sp);
    const int warp = threadIdx.x >> 5;
    const int lane = threadIdx.x & 31;
    const int p = blockIdx.x * WPB + warp;
    const int rowA = __ldg(idx + (2 * p + 0) * D_H);
    const int rowB = __ldg(idx + (2 * p + 1) * D_H);
    processPair<D_H>(x, out, Sp, rowA, rowB, lane);
}

extern "C" void kernel_launch(void* const* d_in, const int* in_sizes, int n_in,
                              void* d_out, int out_size) {
    const float* x     = (const float*)d_in[0];
    const float* S_H   = (const float*)d_in[1];
    const float* S_O   = (const float*)d_in[2];
    const int*   idx_H = (const int*)d_in[3];
    const int*   idx_O = (const int*)d_in[4];
    float* out = (float*)d_out;

    // Concurrent O (L1/latency-bound, 2 blocks/SM) + H (DRAM-bound, high occ):
    // H blocks co-reside in the register/thread headroom left by O blocks.
    cudaStream_t s2;
    cudaEvent_t eFork, eJoin;
    cudaStreamCreateWithFlags(&s2, cudaStreamNonBlocking);
    cudaEventCreateWithFlags(&eFork, cudaEventDisableTiming);
    cudaEventCreateWithFlags(&eJoin, cudaEventDisableTiming);

    cudaEventRecord(eFork, 0);
    cudaStreamWaitEvent(s2, eFork, 0);

    l2norm_O<<<NB_O, BLOCK, 0, s2>>>(x, S_O, idx_O, out);
    l2norm_H<<<NB_H, BLOCK>>>(x, S_H, idx_H, out);

    cudaEventRecord(eJoin, s2);
    cudaStreamWaitEvent((cudaStream_t)0, eJoin, 0);
    // Handles intentionally not destroyed: must outlive graph capture.
}